// round 6
// baseline (speedup 1.0000x reference)
#include <cuda_runtime.h>
#include <cuda_bf16.h>
#include <math.h>

#define BB 4
#define SS 2048
#define DD 1024
#define HH 16
#define HDIM 64
#define NT (BB*SS)   // 8192 tokens
#define PG 40        // gemm smem pitch (bf16) — conflict-free ldmatrix
#define PK 72        // attention smem pitch (bf16)

// ---- bf16 hi/lo scratch (static device globals — allocation-free) ----
__device__ __nv_bfloat16 g_xh[(size_t)NT*DD],  g_xl[(size_t)NT*DD];
__device__ __nv_bfloat16 g_wh[4][(size_t)DD*DD], g_wl[4][(size_t)DD*DD]; // q,k,v,o
__device__ __nv_bfloat16 g_qh[(size_t)NT*HDIM*HH/ HH * HH]; // placeholder sizing below
// (real buffers)
__device__ __nv_bfloat16 g_Qh[(size_t)BB*HH*SS*HDIM], g_Ql[(size_t)BB*HH*SS*HDIM];
__device__ __nv_bfloat16 g_Kh[(size_t)BB*HH*SS*HDIM], g_Kl[(size_t)BB*HH*SS*HDIM];
__device__ __nv_bfloat16 g_Vh[(size_t)BB*HH*SS*HDIM], g_Vl[(size_t)BB*HH*SS*HDIM];
__device__ __nv_bfloat16 g_ah[(size_t)NT*DD],  g_al[(size_t)NT*DD];      // att [t,d]

#define MMA_BF16(d, a, b0, b1)                                             \
    asm("mma.sync.aligned.m16n8k16.row.col.f32.bf16.bf16.f32 "             \
        "{%0,%1,%2,%3}, {%4,%5,%6,%7}, {%8,%9}, {%0,%1,%2,%3};"            \
        : "+f"(d[0]), "+f"(d[1]), "+f"(d[2]), "+f"(d[3])                   \
        : "r"(a[0]), "r"(a[1]), "r"(a[2]), "r"(a[3]), "r"(b0), "r"(b1))

__device__ __forceinline__ void ldsm4(unsigned* r, unsigned a) {
    asm volatile("ldmatrix.sync.aligned.m8n8.x4.shared.b16 {%0,%1,%2,%3}, [%4];"
                 : "=r"(r[0]), "=r"(r[1]), "=r"(r[2]), "=r"(r[3]) : "r"(a));
}
__device__ __forceinline__ void ldsm4t(unsigned* r, unsigned a) {
    asm volatile("ldmatrix.sync.aligned.m8n8.x4.trans.shared.b16 {%0,%1,%2,%3}, [%4];"
                 : "=r"(r[0]), "=r"(r[1]), "=r"(r[2]), "=r"(r[3]) : "r"(a));
}
__device__ __forceinline__ unsigned smem_u32(const void* p) {
    return (unsigned)__cvta_generic_to_shared(p);
}
__device__ __forceinline__ unsigned packbf(__nv_bfloat16 a, __nv_bfloat16 b) {
    __nv_bfloat162 t(a, b);
    return reinterpret_cast<unsigned&>(t);
}
__device__ __forceinline__ void split2(float a, float b, unsigned &h, unsigned &l) {
    __nv_bfloat16 h0 = __float2bfloat16(a), h1 = __float2bfloat16(b);
    h = packbf(h0, h1);
    l = packbf(__float2bfloat16(a - __bfloat162float(h0)),
               __float2bfloat16(b - __bfloat162float(h1)));
}

// ---------------------------------------------------------------------------
// Kernel 0: fp32 -> bf16 hi/lo split. which: 0=x, 1..4=Wq,Wk,Wv,Wo
// ---------------------------------------------------------------------------
__global__ __launch_bounds__(256) void cvt_kernel(const float* __restrict__ src,
                                                  int which, int n)
{
    __nv_bfloat16 *dh, *dl;
    if (which == 0) { dh = g_xh; dl = g_xl; }
    else            { dh = g_wh[which-1]; dl = g_wl[which-1]; }

    int i = (blockIdx.x * 256 + threadIdx.x) * 4;
    if (i >= n) return;
    float4 v = *(const float4*)&src[i];
    unsigned h0, l0, h1, l1;
    split2(v.x, v.y, h0, l0);
    split2(v.z, v.w, h1, l1);
    *(uint2*)&dh[i] = make_uint2(h0, h1);
    *(uint2*)&dl[i] = make_uint2(l0, l1);
}

// ---------------------------------------------------------------------------
// bf16 GEMM mainloop: out[t,n] = sum_k A[t,k]*B[n,k], 3-product hi/lo split.
// 128x128 tile, kc=32, 256 threads (8 warps: 4M x 2N), ldmatrix fragments.
// ---------------------------------------------------------------------------
__device__ __forceinline__ void run_gemm2(
    const __nv_bfloat16* __restrict__ Agh, const __nv_bfloat16* __restrict__ Agl,
    const __nv_bfloat16* __restrict__ Bgh, const __nv_bfloat16* __restrict__ Bgl,
    int t0, int n0,
    __nv_bfloat16* Ah, __nv_bfloat16* Al, __nv_bfloat16* Bh, __nv_bfloat16* Bl,
    float acc[2][8][4])
{
    const int tid  = threadIdx.x;
    const int lane = tid & 31;
    const int warp = tid >> 5;
    const int wm   = warp & 3;
    const int wn   = warp >> 2;
    const int lrow = tid >> 2;    // 0..63
    const int c4   = tid & 3;     // uint4 index within 32-wide k
    const int g = lane >> 3, lr = lane & 7;

    const unsigned aoff = (unsigned)((wm*32 + (g&1)*8 + lr)*PG + (g>>1)*8) * 2;
    const unsigned adAh = smem_u32(Ah) + aoff;
    const unsigned adAl = smem_u32(Al) + aoff;
    const unsigned boff = (unsigned)((wn*64 + (g&1)*8 + lr)*PG + (g>>1)*8) * 2;
    const unsigned adBh = smem_u32(Bh) + boff;
    const unsigned adBl = smem_u32(Bl) + boff;

    uint4 pah[2], pal[2], pbh[2], pbl[2];
    #pragma unroll
    for (int p = 0; p < 2; ++p) {
        size_t ao = (size_t)(t0 + lrow + p*64) * DD + c4*8;
        size_t bo = (size_t)(n0 + lrow + p*64) * DD + c4*8;
        pah[p] = *(const uint4*)&Agh[ao];
        pal[p] = *(const uint4*)&Agl[ao];
        pbh[p] = *(const uint4*)&Bgh[bo];
        pbl[p] = *(const uint4*)&Bgl[bo];
    }

    for (int kc = 0; kc < DD/32; ++kc) {
        #pragma unroll
        for (int p = 0; p < 2; ++p) {
            int row = lrow + p*64;
            *(uint4*)&Ah[row*PG + c4*8] = pah[p];
            *(uint4*)&Al[row*PG + c4*8] = pal[p];
            *(uint4*)&Bh[row*PG + c4*8] = pbh[p];
            *(uint4*)&Bl[row*PG + c4*8] = pbl[p];
        }
        __syncthreads();

        if (kc + 1 < DD/32) {
            const int k0 = (kc + 1) * 32;
            #pragma unroll
            for (int p = 0; p < 2; ++p) {
                size_t ao = (size_t)(t0 + lrow + p*64) * DD + k0 + c4*8;
                size_t bo = (size_t)(n0 + lrow + p*64) * DD + k0 + c4*8;
                pah[p] = *(const uint4*)&Agh[ao];
                pal[p] = *(const uint4*)&Agl[ao];
                pbh[p] = *(const uint4*)&Bgh[bo];
                pbl[p] = *(const uint4*)&Bgl[bo];
            }
        }

        #pragma unroll
        for (int k16 = 0; k16 < 2; ++k16) {
            unsigned af[2][4], afl[2][4];
            #pragma unroll
            for (int am = 0; am < 2; ++am) {
                const unsigned o = (unsigned)(am*16*PG + k16*16) * 2;
                ldsm4(af[am],  adAh + o);
                ldsm4(afl[am], adAl + o);
            }
            #pragma unroll
            for (int jp = 0; jp < 4; ++jp) {
                unsigned bf[4], bfl[4];
                const unsigned o = (unsigned)(jp*16*PG + k16*16) * 2;
                ldsm4(bf,  adBh + o);
                ldsm4(bfl, adBl + o);
                #pragma unroll
                for (int am = 0; am < 2; ++am) {
                    MMA_BF16(acc[am][2*jp],   af[am],  bf[0],  bf[2]);
                    MMA_BF16(acc[am][2*jp],   af[am],  bfl[0], bfl[2]);
                    MMA_BF16(acc[am][2*jp],   afl[am], bf[0],  bf[2]);
                    MMA_BF16(acc[am][2*jp+1], af[am],  bf[1],  bf[3]);
                    MMA_BF16(acc[am][2*jp+1], af[am],  bfl[1], bfl[3]);
                    MMA_BF16(acc[am][2*jp+1], afl[am], bf[1],  bf[3]);
                }
            }
        }
        __syncthreads();
    }
}

// ---------------------------------------------------------------------------
// Kernel 1: QKV projections + bias + fused RoPE -> bf16 hi/lo [b,h,s,hd].
// ---------------------------------------------------------------------------
__global__ __launch_bounds__(256) void qkv_gemm(
    const float* __restrict__ bq, const float* __restrict__ bk,
    const float* __restrict__ bv,
    const float* __restrict__ cosT, const float* __restrict__ sinT)
{
    __shared__ __align__(16) __nv_bfloat16 Ah[128*PG], Al[128*PG], Bh[128*PG], Bl[128*PG];

    const int z = blockIdx.z;
    const float* __restrict__ bp = (z==0) ? bq : (z==1) ? bk : bv;
    __nv_bfloat16* __restrict__ dh = (z==0) ? g_Qh : (z==1) ? g_Kh : g_Vh;
    __nv_bfloat16* __restrict__ dl = (z==0) ? g_Ql : (z==1) ? g_Kl : g_Vl;

    const int t0 = blockIdx.y * 128;
    const int n0 = blockIdx.x * 128;
    const int lane = threadIdx.x & 31;
    const int warp = threadIdx.x >> 5;
    const int wm = warp & 3, wn = warp >> 2;

    float acc[2][8][4] = {};
    run_gemm2(g_xh, g_xl, g_wh[z], g_wl[z], t0, n0, Ah, Al, Bh, Bl, acc);

    const int h = (n0 + wn * 64) >> 6;
    float2 bia[8];
    #pragma unroll
    for (int j = 0; j < 8; ++j)
        bia[j] = *(const float2*)&bp[n0 + wn*64 + j*8 + (lane & 3)*2];

    #pragma unroll
    for (int am = 0; am < 2; ++am) {
        int r0 = t0 + wm*32 + am*16 + (lane >> 2);
        #pragma unroll
        for (int half = 0; half < 2; ++half) {
            int t = r0 + half * 8;
            int b = t >> 11;
            int s = t & (SS - 1);
            size_t base = (((size_t)b*HH + h)*SS + s) * HDIM;
            if (z < 2) {
                #pragma unroll
                for (int j = 0; j < 4; ++j) {
                    int ch = j*8 + (lane & 3)*2;          // < 32
                    float v0a = acc[am][j  ][2*half]   + bia[j].x;
                    float v0b = acc[am][j  ][2*half+1] + bia[j].y;
                    float v1a = acc[am][j+4][2*half]   + bia[j+4].x;
                    float v1b = acc[am][j+4][2*half+1] + bia[j+4].y;
                    float2 c0 = *(const float2*)&cosT[s*HDIM + ch];
                    float2 s0 = *(const float2*)&sinT[s*HDIM + ch];
                    float2 c1 = *(const float2*)&cosT[s*HDIM + ch + 32];
                    float2 s1 = *(const float2*)&sinT[s*HDIM + ch + 32];
                    unsigned hh, ll;
                    split2(v0a*c0.x - v1a*s0.x, v0b*c0.y - v1b*s0.y, hh, ll);
                    *(unsigned*)&dh[base + ch] = hh;
                    *(unsigned*)&dl[base + ch] = ll;
                    split2(v1a*c1.x + v0a*s1.x, v1b*c1.y + v0b*s1.y, hh, ll);
                    *(unsigned*)&dh[base + ch + 32] = hh;
                    *(unsigned*)&dl[base + ch + 32] = ll;
                }
            } else {
                #pragma unroll
                for (int j = 0; j < 8; ++j) {
                    int ch = j*8 + (lane & 3)*2;          // < 64
                    unsigned hh, ll;
                    split2(acc[am][j][2*half] + bia[j].x,
                           acc[am][j][2*half+1] + bia[j].y, hh, ll);
                    *(unsigned*)&dh[base + ch] = hh;
                    *(unsigned*)&dl[base + ch] = ll;
                }
            }
        }
    }
}

// ---------------------------------------------------------------------------
// Kernel 3: output projection -> d_out [t, n] fp32.
// ---------------------------------------------------------------------------
__global__ __launch_bounds__(256) void out_gemm(
    const float* __restrict__ bo, float* __restrict__ out)
{
    __shared__ __align__(16) __nv_bfloat16 Ah[128*PG], Al[128*PG], Bh[128*PG], Bl[128*PG];

    const int t0 = blockIdx.y * 128;
    const int n0 = blockIdx.x * 128;
    const int lane = threadIdx.x & 31;
    const int warp = threadIdx.x >> 5;
    const int wm = warp & 3, wn = warp >> 2;

    float acc[2][8][4] = {};
    run_gemm2(g_ah, g_al, g_wh[3], g_wl[3], t0, n0, Ah, Al, Bh, Bl, acc);

    float2 bia[8];
    #pragma unroll
    for (int j = 0; j < 8; ++j)
        bia[j] = *(const float2*)&bo[n0 + wn*64 + j*8 + (lane & 3)*2];

    #pragma unroll
    for (int am = 0; am < 2; ++am) {
        int r0 = t0 + wm*32 + am*16 + (lane >> 2);
        #pragma unroll
        for (int half = 0; half < 2; ++half) {
            int t = r0 + half * 8;
            #pragma unroll
            for (int j = 0; j < 8; ++j) {
                int n = n0 + wn*64 + j*8 + (lane & 3)*2;
                float2 o;
                o.x = acc[am][j][2*half]   + bia[j].x;
                o.y = acc[am][j][2*half+1] + bia[j].y;
                *(float2*)&out[(size_t)t*DD + n] = o;
            }
        }
    }
}

// ---------------------------------------------------------------------------
// Kernel 2: flash causal attention, bf16 hi/lo inputs (no conversion).
// 128q tile (8 warps x 16 rows) x 64k blocks. grid = (16, 64).
// ---------------------------------------------------------------------------
__global__ __launch_bounds__(256, 2) void attn_mma()
{
    extern __shared__ __align__(16) __nv_bfloat16 smb[];
    __nv_bfloat16* Qh = smb;               // [128][PK]
    __nv_bfloat16* Ql = Qh + 128*PK;
    __nv_bfloat16* Kh = Ql + 128*PK;       // [64][PK]
    __nv_bfloat16* Kl = Kh + 64*PK;
    __nv_bfloat16* Vh = Kl + 64*PK;        // [64][PK]
    __nv_bfloat16* Vl = Vh + 64*PK;

    const int tid  = threadIdx.x;
    const int lane = tid & 31;
    const int warp = tid >> 5;
    const int bh = blockIdx.y;
    const int qt = gridDim.x - 1 - blockIdx.x;   // long tiles first
    const int q0 = qt * 128;

    const size_t hb = (size_t)bh * SS * HDIM;

    // ---- load Q tile (hi/lo) : 128 rows x 64 = 1024 uint4 per buffer
    #pragma unroll
    for (int p = 0; p < 4; ++p) {
        int idx = tid + p*256;
        int row = idx >> 3, c8 = idx & 7;
        *(uint4*)&Qh[row*PK + c8*8] = *(const uint4*)&g_Qh[hb + (size_t)(q0+row)*HDIM + c8*8];
        *(uint4*)&Ql[row*PK + c8*8] = *(const uint4*)&g_Ql[hb + (size_t)(q0+row)*HDIM + c8*8];
    }

    const int g = lane >> 3, lr = lane & 7;
    const unsigned aQoff = (unsigned)((warp*16 + (g&1)*8 + lr)*PK + (g>>1)*8) * 2;
    const unsigned adQh = smem_u32(Qh) + aQoff;
    const unsigned adQl = smem_u32(Ql) + aQoff;
    const unsigned bKoff = (unsigned)(((g&1)*8 + lr)*PK + (g>>1)*8) * 2;
    const unsigned adKh = smem_u32(Kh) + bKoff;
    const unsigned adKl = smem_u32(Kl) + bKoff;
    const unsigned adVh = smem_u32(Vh) + bKoff;
    const unsigned adVl = smem_u32(Vl) + bKoff;

    float O[8][4] = {};
    float m0 = -1e30f, m1 = -1e30f, l0 = 0.f, l1 = 0.f;
    const float C = 0.18033688011112042f;   // (1/8) * log2(e)

    const int nkb = 2*qt + 2;
    for (int kb = 0; kb < nkb; ++kb) {
        const int k0 = kb * 64;
        __syncthreads();
        // ---- load K,V block (hi/lo) : 64 rows x 64 = 512 uint4 per buffer
        #pragma unroll
        for (int p = 0; p < 2; ++p) {
            int idx = tid + p*256;
            int row = idx >> 3, c8 = idx & 7;
            size_t go = hb + (size_t)(k0+row)*HDIM + c8*8;
            *(uint4*)&Kh[row*PK + c8*8] = *(const uint4*)&g_Kh[go];
            *(uint4*)&Kl[row*PK + c8*8] = *(const uint4*)&g_Kl[go];
            *(uint4*)&Vh[row*PK + c8*8] = *(const uint4*)&g_Vh[go];
            *(uint4*)&Vl[row*PK + c8*8] = *(const uint4*)&g_Vl[go];
        }
        __syncthreads();

        // ---- S = Q K^T (qh*kh + qh*kl + ql*kh)
        float z[8][4] = {};
        #pragma unroll
        for (int k16 = 0; k16 < 4; ++k16) {
            unsigned qh[4], ql[4];
            ldsm4(qh, adQh + k16*32);
            ldsm4(ql, adQl + k16*32);
            #pragma unroll
            for (int jp = 0; jp < 4; ++jp) {
                unsigned kh[4], kl[4];
                const unsigned off = (unsigned)(jp*16*PK + k16*16) * 2;
                ldsm4(kh, adKh + off);
                ldsm4(kl, adKl + off);
                MMA_BF16(z[2*jp],   qh, kh[0], kh[2]);
                MMA_BF16(z[2*jp],   qh, kl[0], kl[2]);
                MMA_BF16(z[2*jp],   ql, kh[0], kh[2]);
                MMA_BF16(z[2*jp+1], qh, kh[1], kh[3]);
                MMA_BF16(z[2*jp+1], qh, kl[1], kl[3]);
                MMA_BF16(z[2*jp+1], ql, kh[1], kh[3]);
            }
        }

        // ---- scale (log2 domain) + causal mask
        const bool tail = (kb >= 2*qt);
        #pragma unroll
        for (int j = 0; j < 8; ++j) {
            #pragma unroll
            for (int c = 0; c < 4; ++c) {
                int key = k0 + j*8 + (lane & 3)*2 + (c & 1);
                int row = q0 + warp*16 + (lane >> 2) + (c >> 1)*8;
                z[j][c] = (tail && key > row) ? -1e30f : z[j][c]*C;
            }
        }

        // ---- online softmax
        float ml0 = -1e30f, ml1 = -1e30f;
        #pragma unroll
        for (int j = 0; j < 8; ++j) {
            ml0 = fmaxf(ml0, fmaxf(z[j][0], z[j][1]));
            ml1 = fmaxf(ml1, fmaxf(z[j][2], z[j][3]));
        }
        ml0 = fmaxf(ml0, __shfl_xor_sync(0xffffffffu, ml0, 1));
        ml0 = fmaxf(ml0, __shfl_xor_sync(0xffffffffu, ml0, 2));
        ml1 = fmaxf(ml1, __shfl_xor_sync(0xffffffffu, ml1, 1));
        ml1 = fmaxf(ml1, __shfl_xor_sync(0xffffffffu, ml1, 2));
        float mn0 = fmaxf(m0, ml0), mn1 = fmaxf(m1, ml1);
        float al0 = exp2f(m0 - mn0), al1 = exp2f(m1 - mn1);
        m0 = mn0; m1 = mn1;

        float rs0 = 0.f, rs1 = 0.f;
        #pragma unroll
        for (int j = 0; j < 8; ++j) {
            z[j][0] = exp2f(z[j][0] - mn0);
            z[j][1] = exp2f(z[j][1] - mn0);
            z[j][2] = exp2f(z[j][2] - mn1);
            z[j][3] = exp2f(z[j][3] - mn1);
            rs0 += z[j][0] + z[j][1];
            rs1 += z[j][2] + z[j][3];
        }
        rs0 += __shfl_xor_sync(0xffffffffu, rs0, 1);
        rs0 += __shfl_xor_sync(0xffffffffu, rs0, 2);
        rs1 += __shfl_xor_sync(0xffffffffu, rs1, 1);
        rs1 += __shfl_xor_sync(0xffffffffu, rs1, 2);
        l0 = l0*al0 + rs0;
        l1 = l1*al1 + rs1;
        #pragma unroll
        for (int j = 0; j < 8; ++j) {
            O[j][0] *= al0; O[j][1] *= al0;
            O[j][2] *= al1; O[j][3] *= al1;
        }

        // ---- O += P V (ph*vh + ph*vl + pl*vh)
        #pragma unroll
        for (int k16 = 0; k16 < 4; ++k16) {
            const int f0 = 2*k16, f1 = 2*k16 + 1;
            unsigned ah[4], alr[4];
            split2(z[f0][0], z[f0][1], ah[0], alr[0]);
            split2(z[f0][2], z[f0][3], ah[1], alr[1]);
            split2(z[f1][0], z[f1][1], ah[2], alr[2]);
            split2(z[f1][2], z[f1][3], ah[3], alr[3]);
            #pragma unroll
            for (int jp = 0; jp < 4; ++jp) {
                unsigned vh[4], vl[4];
                const unsigned off = (unsigned)(k16*16*PK + jp*16) * 2;
                ldsm4t(vh, adVh + off);
                ldsm4t(vl, adVl + off);
                MMA_BF16(O[2*jp],   ah,  vh[0], vh[1]);
                MMA_BF16(O[2*jp],   ah,  vl[0], vl[1]);
                MMA_BF16(O[2*jp],   alr, vh[0], vh[1]);
                MMA_BF16(O[2*jp+1], ah,  vh[2], vh[3]);
                MMA_BF16(O[2*jp+1], ah,  vl[2], vl[3]);
                MMA_BF16(O[2*jp+1], alr, vh[2], vh[3]);
            }
        }
    }

    // ---- normalize + write att as bf16 hi/lo [t, d]
    const int b = bh >> 4;
    const int h = bh & 15;
    const float inv0 = 1.f / l0, inv1 = 1.f / l1;
    const int rlo = q0 + warp*16 + (lane >> 2);
    #pragma unroll
    for (int j = 0; j < 8; ++j) {
        int hd = h*HDIM + j*8 + (lane & 3)*2;
        unsigned hh, ll;
        split2(O[j][0]*inv0, O[j][1]*inv0, hh, ll);
        *(unsigned*)&g_ah[((size_t)(b*SS + rlo))*DD + hd] = hh;
        *(unsigned*)&g_al[((size_t)(b*SS + rlo))*DD + hd] = ll;
        split2(O[j][2]*inv1, O[j][3]*inv1, hh, ll);
        *(unsigned*)&g_ah[((size_t)(b*SS + rlo + 8))*DD + hd] = hh;
        *(unsigned*)&g_al[((size_t)(b*SS + rlo + 8))*DD + hd] = ll;
    }
}

// ---------------------------------------------------------------------------
extern "C" void kernel_launch(void* const* d_in, const int* in_sizes, int n_in,
                              void* d_out, int out_size)
{
    const float* x    = (const float*)d_in[0];
    const float* cosT = (const float*)d_in[1];
    const float* sinT = (const float*)d_in[2];
    // d_in[3] = attn_mask (causal — applied analytically)
    const float* Wq = (const float*)d_in[4];
    const float* bq = (const float*)d_in[5];
    const float* Wk = (const float*)d_in[6];
    const float* bk = (const float*)d_in[7];
    const float* Wv = (const float*)d_in[8];
    const float* bv = (const float*)d_in[9];
    const float* Wo = (const float*)d_in[10];
    const float* bo = (const float*)d_in[11];
    float* out = (float*)d_out;

    // 0) precompute bf16 hi/lo splits of x and weights
    cvt_kernel<<<NT*DD/1024, 256>>>(x,  0, NT*DD);
    cvt_kernel<<<DD*DD/1024, 256>>>(Wq, 1, DD*DD);
    cvt_kernel<<<DD*DD/1024, 256>>>(Wk, 2, DD*DD);
    cvt_kernel<<<DD*DD/1024, 256>>>(Wv, 3, DD*DD);
    cvt_kernel<<<DD*DD/1024, 256>>>(Wo, 4, DD*DD);

    // 1) QKV + RoPE -> bf16 hi/lo scratch
    qkv_gemm<<<dim3(DD/128, NT/128, 3), 256>>>(bq, bk, bv, cosT, sinT);

    // 2) causal flash attention -> bf16 hi/lo att
    size_t smem = (size_t)(2*128*PK + 4*64*PK) * sizeof(__nv_bfloat16);  // 73728
    cudaFuncSetAttribute(attn_mma, cudaFuncAttributeMaxDynamicSharedMemorySize, (int)smem);
    attn_mma<<<dim3(SS/128, BB*HH), 256, smem>>>();

    // 3) output projection -> fp32 out
    out_gemm<<<dim3(DD/128, NT/128), 256>>>(bo, out);
}

// round 7
// speedup vs baseline: 1.0233x; 1.0233x over previous
#include <cuda_runtime.h>
#include <cuda_bf16.h>
#include <math.h>

#define BB 4
#define SS 2048
#define DD 1024
#define HH 16
#define HDIM 64
#define NT (BB*SS)   // 8192 tokens
#define PG 40        // gemm smem pitch (bf16) — conflict-free ldmatrix (80B rows)
#define PK 72        // attention smem pitch (bf16)

// ---- bf16 hi/lo scratch (static device globals — allocation-free) ----
__device__ __nv_bfloat16 g_xh[(size_t)NT*DD],  g_xl[(size_t)NT*DD];
__device__ __nv_bfloat16 g_wh[4][(size_t)DD*DD], g_wl[4][(size_t)DD*DD]; // q,k,v,o
__device__ __nv_bfloat16 g_Qh[(size_t)BB*HH*SS*HDIM], g_Ql[(size_t)BB*HH*SS*HDIM];
__device__ __nv_bfloat16 g_Kh[(size_t)BB*HH*SS*HDIM], g_Kl[(size_t)BB*HH*SS*HDIM];
__device__ __nv_bfloat16 g_Vh[(size_t)BB*HH*SS*HDIM], g_Vl[(size_t)BB*HH*SS*HDIM];
__device__ __nv_bfloat16 g_ah[(size_t)NT*DD],  g_al[(size_t)NT*DD];      // att [t,d]

#define MMA_BF16(d, a, b0, b1)                                             \
    asm("mma.sync.aligned.m16n8k16.row.col.f32.bf16.bf16.f32 "             \
        "{%0,%1,%2,%3}, {%4,%5,%6,%7}, {%8,%9}, {%0,%1,%2,%3};"            \
        : "+f"(d[0]), "+f"(d[1]), "+f"(d[2]), "+f"(d[3])                   \
        : "r"(a[0]), "r"(a[1]), "r"(a[2]), "r"(a[3]), "r"(b0), "r"(b1))

__device__ __forceinline__ void ldsm4(unsigned* r, unsigned a) {
    asm volatile("ldmatrix.sync.aligned.m8n8.x4.shared.b16 {%0,%1,%2,%3}, [%4];"
                 : "=r"(r[0]), "=r"(r[1]), "=r"(r[2]), "=r"(r[3]) : "r"(a));
}
__device__ __forceinline__ void ldsm4t(unsigned* r, unsigned a) {
    asm volatile("ldmatrix.sync.aligned.m8n8.x4.trans.shared.b16 {%0,%1,%2,%3}, [%4];"
                 : "=r"(r[0]), "=r"(r[1]), "=r"(r[2]), "=r"(r[3]) : "r"(a));
}
__device__ __forceinline__ unsigned smem_u32(const void* p) {
    return (unsigned)__cvta_generic_to_shared(p);
}
__device__ __forceinline__ unsigned packbf(__nv_bfloat16 a, __nv_bfloat16 b) {
    __nv_bfloat162 t(a, b);
    return reinterpret_cast<unsigned&>(t);
}
__device__ __forceinline__ void split2(float a, float b, unsigned &h, unsigned &l) {
    __nv_bfloat16 h0 = __float2bfloat16(a), h1 = __float2bfloat16(b);
    h = packbf(h0, h1);
    l = packbf(__float2bfloat16(a - __bfloat162float(h0)),
               __float2bfloat16(b - __bfloat162float(h1)));
}
__device__ __forceinline__ void cpa16(unsigned dst, const void* src) {
    asm volatile("cp.async.cg.shared.global [%0], [%1], 16;" :: "r"(dst), "l"(src));
}
#define CP_COMMIT() asm volatile("cp.async.commit_group;")
#define CP_WAIT(N)  asm volatile("cp.async.wait_group %0;" :: "n"(N))

// ---------------------------------------------------------------------------
// Kernel 0: fused fp32 -> bf16 hi/lo split of x and all 4 weights.
// ---------------------------------------------------------------------------
__global__ __launch_bounds__(256) void cvt_all(
    const float* __restrict__ x,
    const float* __restrict__ Wq, const float* __restrict__ Wk,
    const float* __restrict__ Wv, const float* __restrict__ Wo)
{
    const size_t NX = (size_t)NT*DD;
    const size_t NW = (size_t)DD*DD;
    size_t i = ((size_t)blockIdx.x*256 + threadIdx.x) * 4;
    const float* src; __nv_bfloat16 *dh, *dl; size_t off;
    if (i < NX) { src = x; dh = g_xh; dl = g_xl; off = i; }
    else {
        size_t j = i - NX;
        int w = (int)(j / NW);
        off = j - (size_t)w*NW;
        src = (w==0)?Wq:(w==1)?Wk:(w==2)?Wv:Wo;
        dh = g_wh[w]; dl = g_wl[w];
    }
    float4 v = *(const float4*)&src[off];
    unsigned h0, l0, h1, l1;
    split2(v.x, v.y, h0, l0);
    split2(v.z, v.w, h1, l1);
    *(uint2*)&dh[off] = make_uint2(h0, h1);
    *(uint2*)&dl[off] = make_uint2(l0, l1);
}

// ---------------------------------------------------------------------------
// bf16 GEMM mainloop, cp.async double-buffered: out[t,n] = sum_k A[t,k]*B[n,k]
// 128x128 tile, kc=32, 256 threads (8 warps: 4M x 2N). Zero prefetch regs.
// smem: [2 stages][4 arrays (Ah,Al,Bh,Bl)][128*PG]
// ---------------------------------------------------------------------------
#define ARR_BYTES (128*PG*2)          // 10240
#define STAGE_BYTES (4*ARR_BYTES)     // 40960

__device__ __forceinline__ void run_gemm3(
    const __nv_bfloat16* __restrict__ Agh, const __nv_bfloat16* __restrict__ Agl,
    const __nv_bfloat16* __restrict__ Bgh, const __nv_bfloat16* __restrict__ Bgl,
    int t0, int n0, __nv_bfloat16* sm, float acc[2][8][4])
{
    const int tid  = threadIdx.x;
    const int lane = tid & 31;
    const int warp = tid >> 5;
    const int wm   = warp & 3;
    const int wn   = warp >> 2;
    const int row  = tid >> 2;    // 0..63 (+p*64)
    const int q    = tid & 3;     // 16B chunk within 32-wide k
    const int g = lane >> 3, lr = lane & 7;

    const unsigned sbase = smem_u32(sm);
    const unsigned aoff = (unsigned)((wm*32 + (g&1)*8 + lr)*PG + (g>>1)*8) * 2;
    const unsigned boff = (unsigned)((wn*64 + (g&1)*8 + lr)*PG + (g>>1)*8) * 2;

    // issue cp.async loads of k-chunk kc into stage s
    auto issue = [&](int kc, int s) {
        const int k0 = kc * 32;
        const unsigned stg = sbase + (unsigned)s * STAGE_BYTES;
        #pragma unroll
        for (int p = 0; p < 2; ++p) {
            const int r = row + p*64;
            const unsigned d0 = stg + (unsigned)(r*PG + q*8) * 2;
            cpa16(d0,                 Agh + (size_t)(t0 + r)*DD + k0 + q*8);
            cpa16(d0 + ARR_BYTES,     Agl + (size_t)(t0 + r)*DD + k0 + q*8);
            cpa16(d0 + 2*ARR_BYTES,   Bgh + (size_t)(n0 + r)*DD + k0 + q*8);
            cpa16(d0 + 3*ARR_BYTES,   Bgl + (size_t)(n0 + r)*DD + k0 + q*8);
        }
    };

    issue(0, 0);
    CP_COMMIT();

    for (int kc = 0; kc < DD/32; ++kc) {
        const int s = kc & 1;
        if (kc + 1 < DD/32) {
            issue(kc + 1, s ^ 1);
            CP_COMMIT();
            CP_WAIT(1);
        } else {
            CP_WAIT(0);
        }
        __syncthreads();

        const unsigned stg = sbase + (unsigned)s * STAGE_BYTES;
        const unsigned adAh = stg + aoff;
        const unsigned adAl = adAh + ARR_BYTES;
        const unsigned adBh = stg + 2*ARR_BYTES + boff;
        const unsigned adBl = adBh + ARR_BYTES;

        #pragma unroll
        for (int k16 = 0; k16 < 2; ++k16) {
            unsigned af[2][4], afl[2][4];
            #pragma unroll
            for (int am = 0; am < 2; ++am) {
                const unsigned o = (unsigned)(am*16*PG + k16*16) * 2;
                ldsm4(af[am],  adAh + o);
                ldsm4(afl[am], adAl + o);
            }
            #pragma unroll
            for (int jp = 0; jp < 4; ++jp) {
                unsigned bf[4], bfl[4];
                const unsigned o = (unsigned)(jp*16*PG + k16*16) * 2;
                ldsm4(bf,  adBh + o);
                ldsm4(bfl, adBl + o);
                #pragma unroll
                for (int am = 0; am < 2; ++am) {
                    MMA_BF16(acc[am][2*jp],   af[am],  bf[0],  bf[2]);
                    MMA_BF16(acc[am][2*jp],   af[am],  bfl[0], bfl[2]);
                    MMA_BF16(acc[am][2*jp],   afl[am], bf[0],  bf[2]);
                    MMA_BF16(acc[am][2*jp+1], af[am],  bf[1],  bf[3]);
                    MMA_BF16(acc[am][2*jp+1], af[am],  bfl[1], bfl[3]);
                    MMA_BF16(acc[am][2*jp+1], afl[am], bf[1],  bf[3]);
                }
            }
        }
        __syncthreads();
    }
}

// ---------------------------------------------------------------------------
// Kernel 1: QKV projections + bias + fused RoPE -> bf16 hi/lo [b,h,s,hd].
// ---------------------------------------------------------------------------
__global__ __launch_bounds__(256) void qkv_gemm(
    const float* __restrict__ bq, const float* __restrict__ bk,
    const float* __restrict__ bv,
    const float* __restrict__ cosT, const float* __restrict__ sinT)
{
    extern __shared__ __align__(16) __nv_bfloat16 smg[];

    const int z = blockIdx.z;
    const float* __restrict__ bp = (z==0) ? bq : (z==1) ? bk : bv;
    __nv_bfloat16* __restrict__ dh = (z==0) ? g_Qh : (z==1) ? g_Kh : g_Vh;
    __nv_bfloat16* __restrict__ dl = (z==0) ? g_Ql : (z==1) ? g_Kl : g_Vl;

    const int t0 = blockIdx.y * 128;
    const int n0 = blockIdx.x * 128;
    const int lane = threadIdx.x & 31;
    const int warp = threadIdx.x >> 5;
    const int wm = warp & 3, wn = warp >> 2;

    float acc[2][8][4] = {};
    run_gemm3(g_xh, g_xl, g_wh[z], g_wl[z], t0, n0, smg, acc);

    const int h = (n0 + wn * 64) >> 6;
    float2 bia[8];
    #pragma unroll
    for (int j = 0; j < 8; ++j)
        bia[j] = *(const float2*)&bp[n0 + wn*64 + j*8 + (lane & 3)*2];

    #pragma unroll
    for (int am = 0; am < 2; ++am) {
        int r0 = t0 + wm*32 + am*16 + (lane >> 2);
        #pragma unroll
        for (int half = 0; half < 2; ++half) {
            int t = r0 + half * 8;
            int b = t >> 11;
            int s = t & (SS - 1);
            size_t base = (((size_t)b*HH + h)*SS + s) * HDIM;
            if (z < 2) {
                #pragma unroll
                for (int j = 0; j < 4; ++j) {
                    int ch = j*8 + (lane & 3)*2;          // < 32
                    float v0a = acc[am][j  ][2*half]   + bia[j].x;
                    float v0b = acc[am][j  ][2*half+1] + bia[j].y;
                    float v1a = acc[am][j+4][2*half]   + bia[j+4].x;
                    float v1b = acc[am][j+4][2*half+1] + bia[j+4].y;
                    float2 c0 = *(const float2*)&cosT[s*HDIM + ch];
                    float2 s0 = *(const float2*)&sinT[s*HDIM + ch];
                    float2 c1 = *(const float2*)&cosT[s*HDIM + ch + 32];
                    float2 s1 = *(const float2*)&sinT[s*HDIM + ch + 32];
                    unsigned hh, ll;
                    split2(v0a*c0.x - v1a*s0.x, v0b*c0.y - v1b*s0.y, hh, ll);
                    *(unsigned*)&dh[base + ch] = hh;
                    *(unsigned*)&dl[base + ch] = ll;
                    split2(v1a*c1.x + v0a*s1.x, v1b*c1.y + v0b*s1.y, hh, ll);
                    *(unsigned*)&dh[base + ch + 32] = hh;
                    *(unsigned*)&dl[base + ch + 32] = ll;
                }
            } else {
                #pragma unroll
                for (int j = 0; j < 8; ++j) {
                    int ch = j*8 + (lane & 3)*2;          // < 64
                    unsigned hh, ll;
                    split2(acc[am][j][2*half] + bia[j].x,
                           acc[am][j][2*half+1] + bia[j].y, hh, ll);
                    *(unsigned*)&dh[base + ch] = hh;
                    *(unsigned*)&dl[base + ch] = ll;
                }
            }
        }
    }
}

// ---------------------------------------------------------------------------
// Kernel 3: output projection -> d_out [t, n] fp32.
// ---------------------------------------------------------------------------
__global__ __launch_bounds__(256) void out_gemm(
    const float* __restrict__ bo, float* __restrict__ out)
{
    extern __shared__ __align__(16) __nv_bfloat16 smg[];

    const int t0 = blockIdx.y * 128;
    const int n0 = blockIdx.x * 128;
    const int lane = threadIdx.x & 31;
    const int warp = threadIdx.x >> 5;
    const int wm = warp & 3, wn = warp >> 2;

    float acc[2][8][4] = {};
    run_gemm3(g_ah, g_al, g_wh[3], g_wl[3], t0, n0, smg, acc);

    float2 bia[8];
    #pragma unroll
    for (int j = 0; j < 8; ++j)
        bia[j] = *(const float2*)&bo[n0 + wn*64 + j*8 + (lane & 3)*2];

    #pragma unroll
    for (int am = 0; am < 2; ++am) {
        int r0 = t0 + wm*32 + am*16 + (lane >> 2);
        #pragma unroll
        for (int half = 0; half < 2; ++half) {
            int t = r0 + half * 8;
            #pragma unroll
            for (int j = 0; j < 8; ++j) {
                int n = n0 + wn*64 + j*8 + (lane & 3)*2;
                float2 o;
                o.x = acc[am][j][2*half]   + bia[j].x;
                o.y = acc[am][j][2*half+1] + bia[j].y;
                *(float2*)&out[(size_t)t*DD + n] = o;
            }
        }
    }
}

// ---------------------------------------------------------------------------
// Kernel 2: flash causal attention, bf16 hi/lo inputs.
// 128q tile (8 warps x 16 rows) x 64k blocks. grid = (16, 64).
// ---------------------------------------------------------------------------
__global__ __launch_bounds__(256, 2) void attn_mma()
{
    extern __shared__ __align__(16) __nv_bfloat16 smb[];
    __nv_bfloat16* Qh = smb;               // [128][PK]
    __nv_bfloat16* Ql = Qh + 128*PK;
    __nv_bfloat16* Kh = Ql + 128*PK;       // [64][PK]
    __nv_bfloat16* Kl = Kh + 64*PK;
    __nv_bfloat16* Vh = Kl + 64*PK;        // [64][PK]
    __nv_bfloat16* Vl = Vh + 64*PK;

    const int tid  = threadIdx.x;
    const int lane = tid & 31;
    const int warp = tid >> 5;
    const int bh = blockIdx.y;
    const int qt = gridDim.x - 1 - blockIdx.x;   // long tiles first
    const int q0 = qt * 128;

    const size_t hb = (size_t)bh * SS * HDIM;

    #pragma unroll
    for (int p = 0; p < 4; ++p) {
        int idx = tid + p*256;
        int row = idx >> 3, c8 = idx & 7;
        *(uint4*)&Qh[row*PK + c8*8] = *(const uint4*)&g_Qh[hb + (size_t)(q0+row)*HDIM + c8*8];
        *(uint4*)&Ql[row*PK + c8*8] = *(const uint4*)&g_Ql[hb + (size_t)(q0+row)*HDIM + c8*8];
    }

    const int g = lane >> 3, lr = lane & 7;
    const unsigned aQoff = (unsigned)((warp*16 + (g&1)*8 + lr)*PK + (g>>1)*8) * 2;
    const unsigned adQh = smem_u32(Qh) + aQoff;
    const unsigned adQl = smem_u32(Ql) + aQoff;
    const unsigned bKoff = (unsigned)(((g&1)*8 + lr)*PK + (g>>1)*8) * 2;
    const unsigned adKh = smem_u32(Kh) + bKoff;
    const unsigned adKl = smem_u32(Kl) + bKoff;
    const unsigned adVh = smem_u32(Vh) + bKoff;
    const unsigned adVl = smem_u32(Vl) + bKoff;

    float O[8][4] = {};
    float m0 = -1e30f, m1 = -1e30f, l0 = 0.f, l1 = 0.f;
    const float C = 0.18033688011112042f;   // (1/8) * log2(e)

    const int nkb = 2*qt + 2;
    for (int kb = 0; kb < nkb; ++kb) {
        const int k0 = kb * 64;
        __syncthreads();
        #pragma unroll
        for (int p = 0; p < 2; ++p) {
            int idx = tid + p*256;
            int row = idx >> 3, c8 = idx & 7;
            size_t go = hb + (size_t)(k0+row)*HDIM + c8*8;
            *(uint4*)&Kh[row*PK + c8*8] = *(const uint4*)&g_Kh[go];
            *(uint4*)&Kl[row*PK + c8*8] = *(const uint4*)&g_Kl[go];
            *(uint4*)&Vh[row*PK + c8*8] = *(const uint4*)&g_Vh[go];
            *(uint4*)&Vl[row*PK + c8*8] = *(const uint4*)&g_Vl[go];
        }
        __syncthreads();

        // ---- S = Q K^T (qh*kh + qh*kl + ql*kh)
        float z[8][4] = {};
        #pragma unroll
        for (int k16 = 0; k16 < 4; ++k16) {
            unsigned qh[4], ql[4];
            ldsm4(qh, adQh + k16*32);
            ldsm4(ql, adQl + k16*32);
            #pragma unroll
            for (int jp = 0; jp < 4; ++jp) {
                unsigned kh[4], kl[4];
                const unsigned off = (unsigned)(jp*16*PK + k16*16) * 2;
                ldsm4(kh, adKh + off);
                ldsm4(kl, adKl + off);
                MMA_BF16(z[2*jp],   qh, kh[0], kh[2]);
                MMA_BF16(z[2*jp],   qh, kl[0], kl[2]);
                MMA_BF16(z[2*jp],   ql, kh[0], kh[2]);
                MMA_BF16(z[2*jp+1], qh, kh[1], kh[3]);
                MMA_BF16(z[2*jp+1], qh, kl[1], kl[3]);
                MMA_BF16(z[2*jp+1], ql, kh[1], kh[3]);
            }
        }

        const bool tail = (kb >= 2*qt);
        #pragma unroll
        for (int j = 0; j < 8; ++j) {
            #pragma unroll
            for (int c = 0; c < 4; ++c) {
                int key = k0 + j*8 + (lane & 3)*2 + (c & 1);
                int row = q0 + warp*16 + (lane >> 2) + (c >> 1)*8;
                z[j][c] = (tail && key > row) ? -1e30f : z[j][c]*C;
            }
        }

        float ml0 = -1e30f, ml1 = -1e30f;
        #pragma unroll
        for (int j = 0; j < 8; ++j) {
            ml0 = fmaxf(ml0, fmaxf(z[j][0], z[j][1]));
            ml1 = fmaxf(ml1, fmaxf(z[j][2], z[j][3]));
        }
        ml0 = fmaxf(ml0, __shfl_xor_sync(0xffffffffu, ml0, 1));
        ml0 = fmaxf(ml0, __shfl_xor_sync(0xffffffffu, ml0, 2));
        ml1 = fmaxf(ml1, __shfl_xor_sync(0xffffffffu, ml1, 1));
        ml1 = fmaxf(ml1, __shfl_xor_sync(0xffffffffu, ml1, 2));
        float mn0 = fmaxf(m0, ml0), mn1 = fmaxf(m1, ml1);
        float al0 = exp2f(m0 - mn0), al1 = exp2f(m1 - mn1);
        m0 = mn0; m1 = mn1;

        float rs0 = 0.f, rs1 = 0.f;
        #pragma unroll
        for (int j = 0; j < 8; ++j) {
            z[j][0] = exp2f(z[j][0] - mn0);
            z[j][1] = exp2f(z[j][1] - mn0);
            z[j][2] = exp2f(z[j][2] - mn1);
            z[j][3] = exp2f(z[j][3] - mn1);
            rs0 += z[j][0] + z[j][1];
            rs1 += z[j][2] + z[j][3];
        }
        rs0 += __shfl_xor_sync(0xffffffffu, rs0, 1);
        rs0 += __shfl_xor_sync(0xffffffffu, rs0, 2);
        rs1 += __shfl_xor_sync(0xffffffffu, rs1, 1);
        rs1 += __shfl_xor_sync(0xffffffffu, rs1, 2);
        l0 = l0*al0 + rs0;
        l1 = l1*al1 + rs1;
        #pragma unroll
        for (int j = 0; j < 8; ++j) {
            O[j][0] *= al0; O[j][1] *= al0;
            O[j][2] *= al1; O[j][3] *= al1;
        }

        // ---- O += P V (ph*vh + ph*vl + pl*vh)
        #pragma unroll
        for (int k16 = 0; k16 < 4; ++k16) {
            const int f0 = 2*k16, f1 = 2*k16 + 1;
            unsigned ah[4], alr[4];
            split2(z[f0][0], z[f0][1], ah[0], alr[0]);
            split2(z[f0][2], z[f0][3], ah[1], alr[1]);
            split2(z[f1][0], z[f1][1], ah[2], alr[2]);
            split2(z[f1][2], z[f1][3], ah[3], alr[3]);
            #pragma unroll
            for (int jp = 0; jp < 4; ++jp) {
                unsigned vh[4], vl[4];
                const unsigned off = (unsigned)(k16*16*PK + jp*16) * 2;
                ldsm4t(vh, adVh + off);
                ldsm4t(vl, adVl + off);
                MMA_BF16(O[2*jp],   ah,  vh[0], vh[1]);
                MMA_BF16(O[2*jp],   ah,  vl[0], vl[1]);
                MMA_BF16(O[2*jp],   alr, vh[0], vh[1]);
                MMA_BF16(O[2*jp+1], ah,  vh[2], vh[3]);
                MMA_BF16(O[2*jp+1], ah,  vl[2], vl[3]);
                MMA_BF16(O[2*jp+1], alr, vh[2], vh[3]);
            }
        }
    }

    const int b = bh >> 4;
    const int h = bh & 15;
    const float inv0 = 1.f / l0, inv1 = 1.f / l1;
    const int rlo = q0 + warp*16 + (lane >> 2);
    #pragma unroll
    for (int j = 0; j < 8; ++j) {
        int hd = h*HDIM + j*8 + (lane & 3)*2;
        unsigned hh, ll;
        split2(O[j][0]*inv0, O[j][1]*inv0, hh, ll);
        *(unsigned*)&g_ah[((size_t)(b*SS + rlo))*DD + hd] = hh;
        *(unsigned*)&g_al[((size_t)(b*SS + rlo))*DD + hd] = ll;
        split2(O[j][2]*inv1, O[j][3]*inv1, hh, ll);
        *(unsigned*)&g_ah[((size_t)(b*SS + rlo + 8))*DD + hd] = hh;
        *(unsigned*)&g_al[((size_t)(b*SS + rlo + 8))*DD + hd] = ll;
    }
}

// ---------------------------------------------------------------------------
extern "C" void kernel_launch(void* const* d_in, const int* in_sizes, int n_in,
                              void* d_out, int out_size)
{
    const float* x    = (const float*)d_in[0];
    const float* cosT = (const float*)d_in[1];
    const float* sinT = (const float*)d_in[2];
    // d_in[3] = attn_mask (causal — applied analytically)
    const float* Wq = (const float*)d_in[4];
    const float* bq = (const float*)d_in[5];
    const float* Wk = (const float*)d_in[6];
    const float* bk = (const float*)d_in[7];
    const float* Wv = (const float*)d_in[8];
    const float* bv = (const float*)d_in[9];
    const float* Wo = (const float*)d_in[10];
    const float* bo = (const float*)d_in[11];
    float* out = (float*)d_out;

    // 0) fused fp32 -> bf16 hi/lo split (x + 4 weights, one launch)
    const size_t ntotal = (size_t)NT*DD + 4*(size_t)DD*DD;   // 12.6M elems
    cvt_all<<<(int)(ntotal/1024), 256>>>(x, Wq, Wk, Wv, Wo);

    // 1) QKV + RoPE (cp.async pipeline, 80KB dynamic smem)
    const int gsm = 2 * STAGE_BYTES;   // 81920
    cudaFuncSetAttribute(qkv_gemm, cudaFuncAttributeMaxDynamicSharedMemorySize, gsm);
    qkv_gemm<<<dim3(DD/128, NT/128, 3), 256, gsm>>>(bq, bk, bv, cosT, sinT);

    // 2) causal flash attention
    size_t asm_ = (size_t)(2*128*PK + 4*64*PK) * sizeof(__nv_bfloat16);  // 73728
    cudaFuncSetAttribute(attn_mma, cudaFuncAttributeMaxDynamicSharedMemorySize, (int)asm_);
    attn_mma<<<dim3(SS/128, BB*HH), 256, asm_>>>();

    // 3) output projection
    cudaFuncSetAttribute(out_gemm, cudaFuncAttributeMaxDynamicSharedMemorySize, gsm);
    out_gemm<<<dim3(DD/128, NT/128), 256, gsm>>>(bo, out);
}

// round 9
// speedup vs baseline: 1.0780x; 1.0534x over previous
#include <cuda_runtime.h>
#include <cuda_bf16.h>
#include <math.h>

#define BB 4
#define SS 2048
#define DD 1024
#define HH 16
#define HDIM 64
#define NT (BB*SS)   // 8192 tokens
#define PG 40        // gemm smem pitch (bf16) — conflict-free ldmatrix
#define PK 72        // attention smem pitch (bf16)

// ---- bf16 hi/lo scratch (static device globals — allocation-free) ----
__device__ __nv_bfloat16 g_xh[(size_t)NT*DD],  g_xl[(size_t)NT*DD];
__device__ __nv_bfloat16 g_wh[4][(size_t)DD*DD], g_wl[4][(size_t)DD*DD]; // q,k,v,o
__device__ __nv_bfloat16 g_Qh[(size_t)BB*HH*SS*HDIM], g_Ql[(size_t)BB*HH*SS*HDIM];
__device__ __nv_bfloat16 g_Kh[(size_t)BB*HH*SS*HDIM], g_Kl[(size_t)BB*HH*SS*HDIM];
__device__ __nv_bfloat16 g_Vh[(size_t)BB*HH*SS*HDIM], g_Vl[(size_t)BB*HH*SS*HDIM];
__device__ __nv_bfloat16 g_ah[(size_t)NT*DD],  g_al[(size_t)NT*DD];      // att [t,d]

#define MMA_BF16(d, a, b0, b1)                                             \
    asm("mma.sync.aligned.m16n8k16.row.col.f32.bf16.bf16.f32 "             \
        "{%0,%1,%2,%3}, {%4,%5,%6,%7}, {%8,%9}, {%0,%1,%2,%3};"            \
        : "+f"(d[0]), "+f"(d[1]), "+f"(d[2]), "+f"(d[3])                   \
        : "r"(a[0]), "r"(a[1]), "r"(a[2]), "r"(a[3]), "r"(b0), "r"(b1))

__device__ __forceinline__ void ldsm4(unsigned* r, unsigned a) {
    asm volatile("ldmatrix.sync.aligned.m8n8.x4.shared.b16 {%0,%1,%2,%3}, [%4];"
                 : "=r"(r[0]), "=r"(r[1]), "=r"(r[2]), "=r"(r[3]) : "r"(a));
}
__device__ __forceinline__ void ldsm4t(unsigned* r, unsigned a) {
    asm volatile("ldmatrix.sync.aligned.m8n8.x4.trans.shared.b16 {%0,%1,%2,%3}, [%4];"
                 : "=r"(r[0]), "=r"(r[1]), "=r"(r[2]), "=r"(r[3]) : "r"(a));
}
__device__ __forceinline__ unsigned smem_u32(const void* p) {
    return (unsigned)__cvta_generic_to_shared(p);
}
__device__ __forceinline__ unsigned packbf(__nv_bfloat16 a, __nv_bfloat16 b) {
    __nv_bfloat162 t(a, b);
    return reinterpret_cast<unsigned&>(t);
}
__device__ __forceinline__ void split2(float a, float b, unsigned &h, unsigned &l) {
    __nv_bfloat16 h0 = __float2bfloat16(a), h1 = __float2bfloat16(b);
    h = packbf(h0, h1);
    l = packbf(__float2bfloat16(a - __bfloat162float(h0)),
               __float2bfloat16(b - __bfloat162float(h1)));
}
__device__ __forceinline__ void cpa16(unsigned dst, const void* src) {
    asm volatile("cp.async.cg.shared.global [%0], [%1], 16;" :: "r"(dst), "l"(src));
}
#define CP_COMMIT() asm volatile("cp.async.commit_group;")
#define CP_WAIT(N)  asm volatile("cp.async.wait_group %0;" :: "n"(N))

// ---------------------------------------------------------------------------
// Kernel 0: fused fp32 -> bf16 hi/lo split of x and all 4 weights.
// ---------------------------------------------------------------------------
__global__ __launch_bounds__(256) void cvt_all(
    const float* __restrict__ x,
    const float* __restrict__ Wq, const float* __restrict__ Wk,
    const float* __restrict__ Wv, const float* __restrict__ Wo)
{
    const size_t NX = (size_t)NT*DD;
    const size_t NW = (size_t)DD*DD;
    size_t i = ((size_t)blockIdx.x*256 + threadIdx.x) * 4;
    const float* src; __nv_bfloat16 *dh, *dl; size_t off;
    if (i < NX) { src = x; dh = g_xh; dl = g_xl; off = i; }
    else {
        size_t j = i - NX;
        int w = (int)(j / NW);
        off = j - (size_t)w*NW;
        src = (w==0)?Wq:(w==1)?Wk:(w==2)?Wv:Wo;
        dh = g_wh[w]; dl = g_wl[w];
    }
    float4 v = *(const float4*)&src[off];
    unsigned h0, l0, h1, l1;
    split2(v.x, v.y, h0, l0);
    split2(v.z, v.w, h1, l1);
    *(uint2*)&dh[off] = make_uint2(h0, h1);
    *(uint2*)&dl[off] = make_uint2(l0, l1);
}

// ---------------------------------------------------------------------------
// bf16 GEMM mainloop: out[t0+m, n0+n] = sum_k A[.,k]*B[.,k], 3-product split.
// Tile 128M x 64N, k-chunk 32, 256 threads (8 warps x 16 rows x 64 cols).
// cp.async double-buffered. acc[8][4] per thread. Product-major MMA order.
// ---------------------------------------------------------------------------
#define ARR_A (128*PG*2)              // 10240
#define ARR_B (64*PG*2)               // 5120
#define STG4  (2*ARR_A + 2*ARR_B)     // 30720
#define GSM4  (2*STG4)                // 61440

__device__ __forceinline__ void run_gemm4(
    const __nv_bfloat16* __restrict__ Agh, const __nv_bfloat16* __restrict__ Agl,
    const __nv_bfloat16* __restrict__ Bgh, const __nv_bfloat16* __restrict__ Bgl,
    int t0, int n0, unsigned sbase, float acc[8][4])
{
    const int tid  = threadIdx.x;
    const int lane = tid & 31;
    const int warp = tid >> 5;
    const int g = lane >> 3, lr = lane & 7;

    const unsigned aoff = (unsigned)((warp*16 + (g&1)*8 + lr)*PG + (g>>1)*8) * 2;
    const unsigned boff = (unsigned)(((g&1)*8 + lr)*PG + (g>>1)*8) * 2;

    auto issue = [&](int kc, int s) {
        const int k0 = kc * 32;
        const unsigned stg = sbase + (unsigned)s * STG4;
        #pragma unroll
        for (int p = 0; p < 2; ++p) {            // A: 128 rows x 4 16B-chunks
            int idx = tid + p*256;
            int row = idx >> 2, c4 = idx & 3;
            unsigned d = stg + (unsigned)(row*PG + c4*8) * 2;
            cpa16(d,          Agh + (size_t)(t0+row)*DD + k0 + c4*8);
            cpa16(d + ARR_A,  Agl + (size_t)(t0+row)*DD + k0 + c4*8);
        }
        {                                        // B: 64 rows x 4 16B-chunks
            int row = tid >> 2, c4 = tid & 3;
            unsigned d = stg + 2*ARR_A + (unsigned)(row*PG + c4*8) * 2;
            cpa16(d,          Bgh + (size_t)(n0+row)*DD + k0 + c4*8);
            cpa16(d + ARR_B,  Bgl + (size_t)(n0+row)*DD + k0 + c4*8);
        }
    };

    issue(0, 0);
    CP_COMMIT();

    for (int kc = 0; kc < DD/32; ++kc) {
        const int s = kc & 1;
        if (kc + 1 < DD/32) {
            issue(kc + 1, s ^ 1);
            CP_COMMIT();
            CP_WAIT(1);
        } else {
            CP_WAIT(0);
        }
        __syncthreads();

        const unsigned stg  = sbase + (unsigned)s * STG4;
        const unsigned adAh = stg + aoff;
        const unsigned adAl = adAh + ARR_A;
        const unsigned adBh = stg + 2*ARR_A + boff;
        const unsigned adBl = adBh + ARR_B;

        #pragma unroll
        for (int k16 = 0; k16 < 2; ++k16) {
            unsigned af[4], afl[4], bf[4][4], bfl[4][4];
            ldsm4(af,  adAh + k16*32);
            ldsm4(afl, adAl + k16*32);
            #pragma unroll
            for (int jp = 0; jp < 4; ++jp) {
                const unsigned o = (unsigned)(jp*16*PG + k16*16) * 2;
                ldsm4(bf[jp],  adBh + o);
                ldsm4(bfl[jp], adBl + o);
            }
            // product-major: dependency distance 8 MMAs per accumulator
            #pragma unroll
            for (int jp = 0; jp < 4; ++jp) {
                MMA_BF16(acc[2*jp],   af, bf[jp][0], bf[jp][2]);
                MMA_BF16(acc[2*jp+1], af, bf[jp][1], bf[jp][3]);
            }
            #pragma unroll
            for (int jp = 0; jp < 4; ++jp) {
                MMA_BF16(acc[2*jp],   af, bfl[jp][0], bfl[jp][2]);
                MMA_BF16(acc[2*jp+1], af, bfl[jp][1], bfl[jp][3]);
            }
            #pragma unroll
            for (int jp = 0; jp < 4; ++jp) {
                MMA_BF16(acc[2*jp],   afl, bf[jp][0], bf[jp][2]);
                MMA_BF16(acc[2*jp+1], afl, bf[jp][1], bf[jp][3]);
            }
        }
        __syncthreads();
    }
}

// ---------------------------------------------------------------------------
// Kernel 1: QKV projections + bias + fused RoPE -> bf16 hi/lo [b,h,s,hd].
// grid = (NT/128, DD/64, 3)
// ---------------------------------------------------------------------------
__global__ __launch_bounds__(256, 2) void qkv_gemm(
    const float* __restrict__ bq, const float* __restrict__ bk,
    const float* __restrict__ bv,
    const float* __restrict__ cosT, const float* __restrict__ sinT)
{
    extern __shared__ __align__(16) char dsm[];
    const unsigned sbase = smem_u32(dsm);

    const int z = blockIdx.z;
    const float* __restrict__ bp = (z==0) ? bq : (z==1) ? bk : bv;
    __nv_bfloat16* __restrict__ dh = (z==0) ? g_Qh : (z==1) ? g_Kh : g_Vh;
    __nv_bfloat16* __restrict__ dl = (z==0) ? g_Ql : (z==1) ? g_Kl : g_Vl;

    const int t0 = blockIdx.x * 128;
    const int n0 = blockIdx.y * 64;
    const int lane = threadIdx.x & 31;
    const int warp = threadIdx.x >> 5;

    float acc[8][4] = {};
    run_gemm4(g_xh, g_xl, g_wh[z], g_wl[z], t0, n0, sbase, acc);

    const int h = n0 >> 6;
    float2 bia[8];
    #pragma unroll
    for (int j = 0; j < 8; ++j)
        bia[j] = *(const float2*)&bp[n0 + j*8 + (lane & 3)*2];

    const int r0 = t0 + warp*16 + (lane >> 2);
    #pragma unroll
    for (int half = 0; half < 2; ++half) {
        int t = r0 + half * 8;
        int b = t >> 11;
        int s = t & (SS - 1);
        size_t base = (((size_t)b*HH + h)*SS + s) * HDIM;
        if (z < 2) {
            #pragma unroll
            for (int j = 0; j < 4; ++j) {
                int ch = j*8 + (lane & 3)*2;          // < 32
                float v0a = acc[j  ][2*half]   + bia[j].x;
                float v0b = acc[j  ][2*half+1] + bia[j].y;
                float v1a = acc[j+4][2*half]   + bia[j+4].x;
                float v1b = acc[j+4][2*half+1] + bia[j+4].y;
                float2 c0 = *(const float2*)&cosT[s*HDIM + ch];
                float2 s0 = *(const float2*)&sinT[s*HDIM + ch];
                float2 c1 = *(const float2*)&cosT[s*HDIM + ch + 32];
                float2 s1 = *(const float2*)&sinT[s*HDIM + ch + 32];
                unsigned hh, ll;
                split2(v0a*c0.x - v1a*s0.x, v0b*c0.y - v1b*s0.y, hh, ll);
                *(unsigned*)&dh[base + ch] = hh;
                *(unsigned*)&dl[base + ch] = ll;
                split2(v1a*c1.x + v0a*s1.x, v1b*c1.y + v0b*s1.y, hh, ll);
                *(unsigned*)&dh[base + ch + 32] = hh;
                *(unsigned*)&dl[base + ch + 32] = ll;
            }
        } else {
            #pragma unroll
            for (int j = 0; j < 8; ++j) {
                int ch = j*8 + (lane & 3)*2;          // < 64
                unsigned hh, ll;
                split2(acc[j][2*half] + bia[j].x,
                       acc[j][2*half+1] + bia[j].y, hh, ll);
                *(unsigned*)&dh[base + ch] = hh;
                *(unsigned*)&dl[base + ch] = ll;
            }
        }
    }
}

// ---------------------------------------------------------------------------
// Kernel 3: output projection -> d_out [t, n] fp32. grid = (NT/128, DD/64)
// ---------------------------------------------------------------------------
__global__ __launch_bounds__(256, 2) void out_gemm(
    const float* __restrict__ bo, float* __restrict__ out)
{
    extern __shared__ __align__(16) char dsm[];
    const unsigned sbase = smem_u32(dsm);

    const int t0 = blockIdx.x * 128;
    const int n0 = blockIdx.y * 64;
    const int lane = threadIdx.x & 31;
    const int warp = threadIdx.x >> 5;

    float acc[8][4] = {};
    run_gemm4(g_ah, g_al, g_wh[3], g_wl[3], t0, n0, sbase, acc);

    float2 bia[8];
    #pragma unroll
    for (int j = 0; j < 8; ++j)
        bia[j] = *(const float2*)&bo[n0 + j*8 + (lane & 3)*2];

    const int r0 = t0 + warp*16 + (lane >> 2);
    #pragma unroll
    for (int half = 0; half < 2; ++half) {
        int t = r0 + half * 8;
        #pragma unroll
        for (int j = 0; j < 8; ++j) {
            int n = n0 + j*8 + (lane & 3)*2;
            float2 o;
            o.x = acc[j][2*half]   + bia[j].x;
            o.y = acc[j][2*half+1] + bia[j].y;
            *(float2*)&out[(size_t)t*DD + n] = o;
        }
    }
}

// ---------------------------------------------------------------------------
// Kernel 2: flash causal attention, bf16 hi/lo inputs (unchanged from R7).
// ---------------------------------------------------------------------------
__global__ __launch_bounds__(256, 2) void attn_mma()
{
    extern __shared__ __align__(16) __nv_bfloat16 smb[];
    __nv_bfloat16* Qh = smb;               // [128][PK]
    __nv_bfloat16* Ql = Qh + 128*PK;
    __nv_bfloat16* Kh = Ql + 128*PK;       // [64][PK]
    __nv_bfloat16* Kl = Kh + 64*PK;
    __nv_bfloat16* Vh = Kl + 64*PK;        // [64][PK]
    __nv_bfloat16* Vl = Vh + 64*PK;

    const int tid  = threadIdx.x;
    const int lane = tid & 31;
    const int warp = tid >> 5;
    const int bh = blockIdx.y;
    const int qt = gridDim.x - 1 - blockIdx.x;   // long tiles first
    const int q0 = qt * 128;

    const size_t hb = (size_t)bh * SS * HDIM;

    #pragma unroll
    for (int p = 0; p < 4; ++p) {
        int idx = tid + p*256;
        int row = idx >> 3, c8 = idx & 7;
        *(uint4*)&Qh[row*PK + c8*8] = *(const uint4*)&g_Qh[hb + (size_t)(q0+row)*HDIM + c8*8];
        *(uint4*)&Ql[row*PK + c8*8] = *(const uint4*)&g_Ql[hb + (size_t)(q0+row)*HDIM + c8*8];
    }

    const int g = lane >> 3, lr = lane & 7;
    const unsigned aQoff = (unsigned)((warp*16 + (g&1)*8 + lr)*PK + (g>>1)*8) * 2;
    const unsigned adQh = smem_u32(Qh) + aQoff;
    const unsigned adQl = smem_u32(Ql) + aQoff;
    const unsigned bKoff = (unsigned)(((g&1)*8 + lr)*PK + (g>>1)*8) * 2;
    const unsigned adKh = smem_u32(Kh) + bKoff;
    const unsigned adKl = smem_u32(Kl) + bKoff;
    const unsigned adVh = smem_u32(Vh) + bKoff;
    const unsigned adVl = smem_u32(Vl) + bKoff;

    float O[8][4] = {};
    float m0 = -1e30f, m1 = -1e30f, l0 = 0.f, l1 = 0.f;
    const float C = 0.18033688011112042f;   // (1/8) * log2(e)

    const int nkb = 2*qt + 2;
    for (int kb = 0; kb < nkb; ++kb) {
        const int k0 = kb * 64;
        __syncthreads();
        #pragma unroll
        for (int p = 0; p < 2; ++p) {
            int idx = tid + p*256;
            int row = idx >> 3, c8 = idx & 7;
            size_t go = hb + (size_t)(k0+row)*HDIM + c8*8;
            *(uint4*)&Kh[row*PK + c8*8] = *(const uint4*)&g_Kh[go];
            *(uint4*)&Kl[row*PK + c8*8] = *(const uint4*)&g_Kl[go];
            *(uint4*)&Vh[row*PK + c8*8] = *(const uint4*)&g_Vh[go];
            *(uint4*)&Vl[row*PK + c8*8] = *(const uint4*)&g_Vl[go];
        }
        __syncthreads();

        float z[8][4] = {};
        #pragma unroll
        for (int k16 = 0; k16 < 4; ++k16) {
            unsigned qh[4], ql[4];
            ldsm4(qh, adQh + k16*32);
            ldsm4(ql, adQl + k16*32);
            #pragma unroll
            for (int jp = 0; jp < 4; ++jp) {
                unsigned kh[4], kl[4];
                const unsigned off = (unsigned)(jp*16*PK + k16*16) * 2;
                ldsm4(kh, adKh + off);
                ldsm4(kl, adKl + off);
                MMA_BF16(z[2*jp],   qh, kh[0], kh[2]);
                MMA_BF16(z[2*jp],   qh, kl[0], kl[2]);
                MMA_BF16(z[2*jp],   ql, kh[0], kh[2]);
                MMA_BF16(z[2*jp+1], qh, kh[1], kh[3]);
                MMA_BF16(z[2*jp+1], qh, kl[1], kl[3]);
                MMA_BF16(z[2*jp+1], ql, kh[1], kh[3]);
            }
        }

        const bool tail = (kb >= 2*qt);
        #pragma unroll
        for (int j = 0; j < 8; ++j) {
            #pragma unroll
            for (int c = 0; c < 4; ++c) {
                int key = k0 + j*8 + (lane & 3)*2 + (c & 1);
                int row = q0 + warp*16 + (lane >> 2) + (c >> 1)*8;
                z[j][c] = (tail && key > row) ? -1e30f : z[j][c]*C;
            }
        }

        float ml0 = -1e30f, ml1 = -1e30f;
        #pragma unroll
        for (int j = 0; j < 8; ++j) {
            ml0 = fmaxf(ml0, fmaxf(z[j][0], z[j][1]));
            ml1 = fmaxf(ml1, fmaxf(z[j][2], z[j][3]));
        }
        ml0 = fmaxf(ml0, __shfl_xor_sync(0xffffffffu, ml0, 1));
        ml0 = fmaxf(ml0, __shfl_xor_sync(0xffffffffu, ml0, 2));
        ml1 = fmaxf(ml1, __shfl_xor_sync(0xffffffffu, ml1, 1));
        ml1 = fmaxf(ml1, __shfl_xor_sync(0xffffffffu, ml1, 2));
        float mn0 = fmaxf(m0, ml0), mn1 = fmaxf(m1, ml1);
        float al0 = exp2f(m0 - mn0), al1 = exp2f(m1 - mn1);
        m0 = mn0; m1 = mn1;

        float rs0 = 0.f, rs1 = 0.f;
        #pragma unroll
        for (int j = 0; j < 8; ++j) {
            z[j][0] = exp2f(z[j][0] - mn0);
            z[j][1] = exp2f(z[j][1] - mn0);
            z[j][2] = exp2f(z[j][2] - mn1);
            z[j][3] = exp2f(z[j][3] - mn1);
            rs0 += z[j][0] + z[j][1];
            rs1 += z[j][2] + z[j][3];
        }
        rs0 += __shfl_xor_sync(0xffffffffu, rs0, 1);
        rs0 += __shfl_xor_sync(0xffffffffu, rs0, 2);
        rs1 += __shfl_xor_sync(0xffffffffu, rs1, 1);
        rs1 += __shfl_xor_sync(0xffffffffu, rs1, 2);
        l0 = l0*al0 + rs0;
        l1 = l1*al1 + rs1;
        #pragma unroll
        for (int j = 0; j < 8; ++j) {
            O[j][0] *= al0; O[j][1] *= al0;
            O[j][2] *= al1; O[j][3] *= al1;
        }

        #pragma unroll
        for (int k16 = 0; k16 < 4; ++k16) {
            const int f0 = 2*k16, f1 = 2*k16 + 1;
            unsigned ah[4], alr[4];
            split2(z[f0][0], z[f0][1], ah[0], alr[0]);
            split2(z[f0][2], z[f0][3], ah[1], alr[1]);
            split2(z[f1][0], z[f1][1], ah[2], alr[2]);
            split2(z[f1][2], z[f1][3], ah[3], alr[3]);
            #pragma unroll
            for (int jp = 0; jp < 4; ++jp) {
                unsigned vh[4], vl[4];
                const unsigned off = (unsigned)(k16*16*PK + jp*16) * 2;
                ldsm4t(vh, adVh + off);
                ldsm4t(vl, adVl + off);
                MMA_BF16(O[2*jp],   ah,  vh[0], vh[1]);
                MMA_BF16(O[2*jp],   ah,  vl[0], vl[1]);
                MMA_BF16(O[2*jp],   alr, vh[0], vh[1]);
                MMA_BF16(O[2*jp+1], ah,  vh[2], vh[3]);
                MMA_BF16(O[2*jp+1], ah,  vl[2], vl[3]);
                MMA_BF16(O[2*jp+1], alr, vh[2], vh[3]);
            }
        }
    }

    const int b = bh >> 4;
    const int h = bh & 15;
    const float inv0 = 1.f / l0, inv1 = 1.f / l1;
    const int rlo = q0 + warp*16 + (lane >> 2);
    #pragma unroll
    for (int j = 0; j < 8; ++j) {
        int hd = h*HDIM + j*8 + (lane & 3)*2;
        unsigned hh, ll;
        split2(O[j][0]*inv0, O[j][1]*inv0, hh, ll);
        *(unsigned*)&g_ah[((size_t)(b*SS + rlo))*DD + hd] = hh;
        *(unsigned*)&g_al[((size_t)(b*SS + rlo))*DD + hd] = ll;
        split2(O[j][2]*inv1, O[j][3]*inv1, hh, ll);
        *(unsigned*)&g_ah[((size_t)(b*SS + rlo + 8))*DD + hd] = hh;
        *(unsigned*)&g_al[((size_t)(b*SS + rlo + 8))*DD + hd] = ll;
    }
}

// ---------------------------------------------------------------------------
extern "C" void kernel_launch(void* const* d_in, const int* in_sizes, int n_in,
                              void* d_out, int out_size)
{
    const float* x    = (const float*)d_in[0];
    const float* cosT = (const float*)d_in[1];
    const float* sinT = (const float*)d_in[2];
    // d_in[3] = attn_mask (causal — applied analytically)
    const float* Wq = (const float*)d_in[4];
    const float* bq = (const float*)d_in[5];
    const float* Wk = (const float*)d_in[6];
    const float* bk = (const float*)d_in[7];
    const float* Wv = (const float*)d_in[8];
    const float* bv = (const float*)d_in[9];
    const float* Wo = (const float*)d_in[10];
    const float* bo = (const float*)d_in[11];
    float* out = (float*)d_out;

    // 0) fused fp32 -> bf16 hi/lo split
    const size_t ntotal = (size_t)NT*DD + 4*(size_t)DD*DD;
    cvt_all<<<(int)(ntotal/1024), 256>>>(x, Wq, Wk, Wv, Wo);

    // 1) QKV + RoPE
    cudaFuncSetAttribute(qkv_gemm, cudaFuncAttributeMaxDynamicSharedMemorySize, GSM4);
    qkv_gemm<<<dim3(NT/128, DD/64, 3), 256, GSM4>>>(bq, bk, bv, cosT, sinT);

    // 2) causal flash attention
    size_t asm_ = (size_t)(2*128*PK + 4*64*PK) * sizeof(__nv_bfloat16);  // 73728
    cudaFuncSetAttribute(attn_mma, cudaFuncAttributeMaxDynamicSharedMemorySize, (int)asm_);
    attn_mma<<<dim3(SS/128, BB*HH), 256, asm_>>>();

    // 3) output projection
    cudaFuncSetAttribute(out_gemm, cudaFuncAttributeMaxDynamicSharedMemorySize, GSM4);
    out_gemm<<<dim3(NT/128, DD/64), 256, GSM4>>>(bo, out);
}